// round 1
// baseline (speedup 1.0000x reference)
#include <cuda_runtime.h>
#include <math.h>

#define NN 100000
#define EE 1600000
#define GG 128
#define LL 8
#define DD 128

// ---------------- scratch (device globals; no allocation allowed) ----------
__device__ float g_bufA[NN * DD];   // node features (pre-BN output of aggregate)
__device__ float g_bufB[NN * DD];   // hw = (h@W)*ns
__device__ int   g_out_deg[NN];
__device__ int   g_in_deg[NN];
__device__ float g_ns[NN];
__device__ float g_nd[NN];
__device__ int   g_row_ptr[NN + 1];
__device__ int   g_cursor[NN];
__device__ int   g_csr_src[EE];
__device__ float g_bn_sum[LL][DD];
__device__ float g_bn_sq[LL][DD];
__device__ float g_bn_scale[LL][DD];
__device__ float g_bn_shift[LL][DD];
__device__ float g_pool_sum[GG * DD];
__device__ float g_pool_cnt[GG];

// ---------------- init: zero everything that is accumulated into ----------
__global__ void k_init() {
    int i = blockIdx.x * blockDim.x + threadIdx.x;
    int stride = gridDim.x * blockDim.x;
    for (int j = i; j < NN; j += stride) { g_out_deg[j] = 0; g_in_deg[j] = 0; }
    for (int j = i; j < LL * DD; j += stride) {
        ((float*)g_bn_sum)[j] = 0.f;
        ((float*)g_bn_sq)[j] = 0.f;
    }
    for (int j = i; j < GG * DD; j += stride) g_pool_sum[j] = 0.f;
    for (int j = i; j < GG; j += stride) g_pool_cnt[j] = 0.f;
}

// ---------------- degree counting ----------
__global__ void k_degree(const int* __restrict__ src, const int* __restrict__ dst) {
    int i = blockIdx.x * blockDim.x + threadIdx.x;
    if (i < EE) {
        atomicAdd(&g_out_deg[src[i]], 1);
        atomicAdd(&g_in_deg[dst[i]], 1);
    }
}

// ---------------- single-block exclusive scan of in-degree -> row_ptr ------
__global__ void k_scan() {
    __shared__ int wsum[32];
    __shared__ int s_running;
    int tid = threadIdx.x, lane = tid & 31, wid = tid >> 5;
    if (tid == 0) s_running = 0;
    __syncthreads();
    for (int base = 0; base < NN; base += 1024) {
        int i = base + tid;
        int v = (i < NN) ? g_in_deg[i] : 0;
        int incl = v;
#pragma unroll
        for (int off = 1; off < 32; off <<= 1) {
            int t = __shfl_up_sync(0xffffffffu, incl, off);
            if (lane >= off) incl += t;
        }
        if (lane == 31) wsum[wid] = incl;
        __syncthreads();
        if (wid == 0) {
            int s = wsum[lane];
#pragma unroll
            for (int off = 1; off < 32; off <<= 1) {
                int t = __shfl_up_sync(0xffffffffu, s, off);
                if (lane >= off) s += t;
            }
            wsum[lane] = s;
        }
        __syncthreads();
        int woff = wid ? wsum[wid - 1] : 0;
        int run = s_running;
        int excl = run + woff + incl - v;
        if (i < NN) { g_row_ptr[i] = excl; g_cursor[i] = excl; }
        __syncthreads();
        if (tid == 0) s_running = run + wsum[31];
        __syncthreads();
    }
    if (threadIdx.x == 0) g_row_ptr[NN] = s_running;
}

// ---------------- norms ----------
__global__ void k_norms() {
    int i = blockIdx.x * blockDim.x + threadIdx.x;
    if (i < NN) {
        g_ns[i] = rsqrtf((float)max(g_out_deg[i], 1));
        g_nd[i] = rsqrtf((float)max(g_in_deg[i], 1));
    }
}

// ---------------- CSR fill ----------
__global__ void k_fill(const int* __restrict__ src, const int* __restrict__ dst) {
    int i = blockIdx.x * blockDim.x + threadIdx.x;
    if (i < EE) {
        int d = dst[i];
        int p = atomicAdd(&g_cursor[d], 1);
        g_csr_src[p] = src[i];
    }
}

// ---------------- GEMM: hw = transform(h) @ W  * ns[row] -------------------
// transform = embed gather (layer 0) or BN(prev layer)+tanh (layer>0).
// Tile: 64 rows x 128 cols, K tiled by 32. 256 threads, 4x8 register tile.
__global__ void k_gemm(const float* __restrict__ W,
                       const float* __restrict__ embed,
                       const int* __restrict__ x,
                       int layer) {
    const int BM = 64, BK = 32;
    __shared__ float As[BK][BM + 4];     // [k][row]
    __shared__ float Wsh[BK][DD + 4];    // [k][col]
    int tid = threadIdx.x;
    int row0 = blockIdx.x * BM;
    int rg = tid >> 4;   // 0..15
    int cg = tid & 15;   // 0..15

    float acc[4][8];
#pragma unroll
    for (int i = 0; i < 4; i++)
#pragma unroll
        for (int j = 0; j < 8; j++) acc[i][j] = 0.f;

    for (int k0 = 0; k0 < DD; k0 += BK) {
        // load A tile (transposed) with input transform applied
        for (int idx = tid; idx < BM * BK; idx += 256) {
            int r = idx >> 5;        // 0..63
            int kk = idx & 31;       // 0..31
            int row = row0 + r;
            int k = k0 + kk;
            float v = 0.f;
            if (row < NN) {
                if (layer == 0) {
                    v = embed[x[row] * DD + k];
                } else {
                    v = g_bufA[row * DD + k];
                    v = tanhf(fmaf(v, g_bn_scale[layer - 1][k], g_bn_shift[layer - 1][k]));
                }
            }
            As[kk][r] = v;
        }
        // load W tile
        for (int idx = tid; idx < BK * DD; idx += 256) {
            int kk = idx >> 7;      // 0..31
            int c = idx & 127;      // 0..127
            Wsh[kk][c] = W[(k0 + kk) * DD + c];
        }
        __syncthreads();
#pragma unroll
        for (int kk = 0; kk < BK; kk++) {
            float4 a4 = *(const float4*)&As[kk][rg * 4];
            float4 b4 = *(const float4*)&Wsh[kk][cg * 8];
            float4 c4 = *(const float4*)&Wsh[kk][cg * 8 + 4];
            float av[4] = {a4.x, a4.y, a4.z, a4.w};
            float wv[8] = {b4.x, b4.y, b4.z, b4.w, c4.x, c4.y, c4.z, c4.w};
#pragma unroll
            for (int i = 0; i < 4; i++)
#pragma unroll
                for (int j = 0; j < 8; j++)
                    acc[i][j] = fmaf(av[i], wv[j], acc[i][j]);
        }
        __syncthreads();
    }
    // epilogue: multiply by ns[row], store
#pragma unroll
    for (int i = 0; i < 4; i++) {
        int row = row0 + rg * 4 + i;
        if (row < NN) {
            float nsv = g_ns[row];
            float4 o0 = {acc[i][0] * nsv, acc[i][1] * nsv, acc[i][2] * nsv, acc[i][3] * nsv};
            float4 o1 = {acc[i][4] * nsv, acc[i][5] * nsv, acc[i][6] * nsv, acc[i][7] * nsv};
            *(float4*)&g_bufB[row * DD + cg * 8] = o0;
            *(float4*)&g_bufB[row * DD + cg * 8 + 4] = o1;
        }
    }
}

// ---------------- aggregate: bufA = (sum_{in-edges} hw[src]) * nd + b, *snorm
// warp per dst node, lane handles 4 features. Also accumulates BN stats.
__global__ void k_agg(const float* __restrict__ bs,
                      const float* __restrict__ snorm_n,
                      int layer) {
    __shared__ float s_sum[8][DD];
    __shared__ float s_sq[8][DD];
    int w = threadIdx.x >> 5;
    int lane = threadIdx.x & 31;
    int node = blockIdx.x * 8 + w;

    float4 r = {0.f, 0.f, 0.f, 0.f};
    if (node < NN) {
        float4 acc = {0.f, 0.f, 0.f, 0.f};
        int start = g_row_ptr[node];
        int end = g_row_ptr[node + 1];
        for (int base = start; base < end; base += 32) {
            int e = base + lane;
            int s = (e < end) ? g_csr_src[e] : 0;
            int cnt = min(32, end - base);
            for (int j = 0; j < cnt; j++) {
                int sj = __shfl_sync(0xffffffffu, s, j);
                float4 v = *(const float4*)&g_bufB[sj * DD + lane * 4];
                acc.x += v.x; acc.y += v.y; acc.z += v.z; acc.w += v.w;
            }
        }
        float ndv = g_nd[node];
        float sn = snorm_n[node];
        float4 b = *(const float4*)&bs[layer * DD + lane * 4];
        r.x = fmaf(acc.x, ndv, b.x) * sn;
        r.y = fmaf(acc.y, ndv, b.y) * sn;
        r.z = fmaf(acc.z, ndv, b.z) * sn;
        r.w = fmaf(acc.w, ndv, b.w) * sn;
        *(float4*)&g_bufA[node * DD + lane * 4] = r;
    }
    // BN partial stats
    int f0 = lane * 4;
    s_sum[w][f0 + 0] = r.x; s_sum[w][f0 + 1] = r.y; s_sum[w][f0 + 2] = r.z; s_sum[w][f0 + 3] = r.w;
    s_sq[w][f0 + 0] = r.x * r.x; s_sq[w][f0 + 1] = r.y * r.y;
    s_sq[w][f0 + 2] = r.z * r.z; s_sq[w][f0 + 3] = r.w * r.w;
    __syncthreads();
    if (threadIdx.x < DD) {
        int f = threadIdx.x;
        float s = 0.f, q = 0.f;
#pragma unroll
        for (int ww = 0; ww < 8; ww++) { s += s_sum[ww][f]; q += s_sq[ww][f]; }
        atomicAdd(&g_bn_sum[layer][f], s);
        atomicAdd(&g_bn_sq[layer][f], q);
    }
}

// ---------------- BN finalize ----------
__global__ void k_bn(const float* __restrict__ gammas,
                     const float* __restrict__ betas, int layer) {
    int f = threadIdx.x;
    float mean = g_bn_sum[layer][f] * (1.f / NN);
    float var = g_bn_sq[layer][f] * (1.f / NN) - mean * mean;
    float rstd = rsqrtf(var + 1e-5f);
    float scale = rstd * gammas[layer * DD + f];
    g_bn_scale[layer][f] = scale;
    g_bn_shift[layer][f] = betas[layer * DD + f] - mean * scale;
}

// ---------------- graph mean pooling (graph_ids sorted) ----------
__global__ void k_pool(const int* __restrict__ gid) {
    int f = threadIdx.x;                 // 0..127
    int base = blockIdx.x * 32;
    float acc = 0.f;
    int cur = gid[base];
    float sc = g_bn_scale[LL - 1][f];
    float sh = g_bn_shift[LL - 1][f];
    for (int i = 0; i < 32; i++) {
        int node = base + i;
        if (node >= NN) break;
        int g = gid[node];
        if (g != cur) {
            atomicAdd(&g_pool_sum[cur * DD + f], acc);
            acc = 0.f;
            cur = g;
        }
        float v = g_bufA[node * DD + f];
        acc += tanhf(fmaf(v, sc, sh));
    }
    atomicAdd(&g_pool_sum[cur * DD + f], acc);
    if (f == 0) {
        float c = 0.f;
        int cur2 = gid[base];
        for (int i = 0; i < 32; i++) {
            int node = base + i;
            if (node >= NN) break;
            int g = gid[node];
            if (g != cur2) {
                atomicAdd(&g_pool_cnt[cur2], c);
                c = 0.f;
                cur2 = g;
            }
            c += 1.f;
        }
        atomicAdd(&g_pool_cnt[cur2], c);
    }
}

// ---------------- readout MLP: relu(mean) -> relu(@r1) -> @r2 --------------
__global__ void k_mlp(const float* __restrict__ r1w, const float* __restrict__ r1b,
                      const float* __restrict__ r2w, const float* __restrict__ r2b,
                      float* __restrict__ out) {
    __shared__ float hg[DD];
    __shared__ float z[64];
    int g = blockIdx.x;
    int t = threadIdx.x;  // 0..63
    float cnt = fmaxf(g_pool_cnt[g], 1.f);
    for (int f = t; f < DD; f += 64)
        hg[f] = fmaxf(g_pool_sum[g * DD + f] / cnt, 0.f);
    __syncthreads();
    float d = r1b[t];
#pragma unroll 8
    for (int f = 0; f < DD; f++) d = fmaf(hg[f], r1w[t * DD + f], d);
    z[t] = fmaxf(d, 0.f);
    __syncthreads();
    if (t == 0) {
        float o = r2b[0];
#pragma unroll 8
        for (int i = 0; i < 64; i++) o = fmaf(z[i], r2w[i], o);
        out[g] = o;
    }
}

// ---------------- host ----------
extern "C" void kernel_launch(void* const* d_in, const int* in_sizes, int n_in,
                              void* d_out, int out_size) {
    const int* x = (const int*)d_in[0];
    // d_in[1] = e (unused by reference)
    const int* src = (const int*)d_in[2];
    const int* dst = (const int*)d_in[3];
    const int* gid = (const int*)d_in[4];
    const float* snorm_n = (const float*)d_in[5];
    // d_in[6] = snorm_e (unused)
    const float* embed = (const float*)d_in[7];
    const float* Ws = (const float*)d_in[8];
    const float* bs = (const float*)d_in[9];
    const float* gammas = (const float*)d_in[10];
    const float* betas = (const float*)d_in[11];
    const float* r1w = (const float*)d_in[12];
    const float* r1b = (const float*)d_in[13];
    const float* r2w = (const float*)d_in[14];
    const float* r2b = (const float*)d_in[15];
    float* out = (float*)d_out;

    k_init<<<256, 256>>>();
    k_degree<<<(EE + 255) / 256, 256>>>(src, dst);
    k_scan<<<1, 1024>>>();
    k_norms<<<(NN + 255) / 256, 256>>>();
    k_fill<<<(EE + 255) / 256, 256>>>(src, dst);

    for (int l = 0; l < LL; l++) {
        k_gemm<<<(NN + 63) / 64, 256>>>(Ws + l * DD * DD, embed, x, l);
        k_agg<<<(NN + 7) / 8, 256>>>(bs, snorm_n, l);
        k_bn<<<1, DD>>>(gammas, betas, l);
    }
    k_pool<<<(NN + 31) / 32, DD>>>(gid);
    k_mlp<<<GG, 64>>>(r1w, r1b, r2w, r2b, out);
}

// round 4
// speedup vs baseline: 1.2138x; 1.2138x over previous
#include <cuda_runtime.h>
#include <math.h>
#include <stdint.h>

#define NN 100000
#define EE 1600000
#define GG 128
#define LL 8
#define DD 128

// ---------------- scratch (device globals; no allocation allowed) ----------
__device__ float g_bufA[NN * DD];   // node features (pre-BN output of aggregate)
__device__ float g_bufB[NN * DD];   // hw = (h@W)*ns
__device__ int   g_out_deg[NN];
__device__ int   g_in_deg[NN];
__device__ float g_ns[NN];
__device__ float g_nd[NN];
__device__ int   g_row_ptr[NN + 1];
__device__ int   g_cursor[NN];
__device__ int   g_csr_src[EE];
__device__ float g_bn_sum[LL][DD];
__device__ float g_bn_sq[LL][DD];
__device__ float g_bn_scale[LL][DD];
__device__ float g_bn_shift[LL][DD];
__device__ float g_pool_sum[GG * DD];
__device__ float g_pool_cnt[GG];

// ---------------- init ----------
__global__ void k_init() {
    int i = blockIdx.x * blockDim.x + threadIdx.x;
    int stride = gridDim.x * blockDim.x;
    for (int j = i; j < NN; j += stride) { g_out_deg[j] = 0; g_in_deg[j] = 0; }
    for (int j = i; j < LL * DD; j += stride) {
        ((float*)g_bn_sum)[j] = 0.f;
        ((float*)g_bn_sq)[j] = 0.f;
    }
    for (int j = i; j < GG * DD; j += stride) g_pool_sum[j] = 0.f;
    for (int j = i; j < GG; j += stride) g_pool_cnt[j] = 0.f;
}

// ---------------- degree counting ----------
__global__ void k_degree(const int* __restrict__ src, const int* __restrict__ dst) {
    int i = blockIdx.x * blockDim.x + threadIdx.x;
    if (i < EE) {
        atomicAdd(&g_out_deg[src[i]], 1);
        atomicAdd(&g_in_deg[dst[i]], 1);
    }
}

// ---------------- single-block exclusive scan of in-degree -> row_ptr ------
__global__ void k_scan() {
    __shared__ int wsum[32];
    __shared__ int s_running;
    int tid = threadIdx.x, lane = tid & 31, wid = tid >> 5;
    if (tid == 0) s_running = 0;
    __syncthreads();
    for (int base = 0; base < NN; base += 1024) {
        int i = base + tid;
        int v = (i < NN) ? g_in_deg[i] : 0;
        int incl = v;
#pragma unroll
        for (int off = 1; off < 32; off <<= 1) {
            int t = __shfl_up_sync(0xffffffffu, incl, off);
            if (lane >= off) incl += t;
        }
        if (lane == 31) wsum[wid] = incl;
        __syncthreads();
        if (wid == 0) {
            int s = wsum[lane];
#pragma unroll
            for (int off = 1; off < 32; off <<= 1) {
                int t = __shfl_up_sync(0xffffffffu, s, off);
                if (lane >= off) s += t;
            }
            wsum[lane] = s;
        }
        __syncthreads();
        int woff = wid ? wsum[wid - 1] : 0;
        int run = s_running;
        int excl = run + woff + incl - v;
        if (i < NN) { g_row_ptr[i] = excl; g_cursor[i] = excl; }
        __syncthreads();
        if (tid == 0) s_running = run + wsum[31];
        __syncthreads();
    }
    if (threadIdx.x == 0) g_row_ptr[NN] = s_running;
}

// ---------------- norms ----------
__global__ void k_norms() {
    int i = blockIdx.x * blockDim.x + threadIdx.x;
    if (i < NN) {
        g_ns[i] = rsqrtf((float)max(g_out_deg[i], 1));
        g_nd[i] = rsqrtf((float)max(g_in_deg[i], 1));
    }
}

// ---------------- CSR fill ----------
__global__ void k_fill(const int* __restrict__ src, const int* __restrict__ dst) {
    int i = blockIdx.x * blockDim.x + threadIdx.x;
    if (i < EE) {
        int d = dst[i];
        int p = atomicAdd(&g_cursor[d], 1);
        g_csr_src[p] = src[i];
    }
}

// ---------------- 3xTF32 tensor-core GEMM ----------------------------------
// hw = transform(h) @ W * ns[row]. Block: 128 rows, 8 warps x 16 rows.
// Error-compensated tf32: v = hi + lo, c += lo_a*hi_b + hi_a*lo_b + hi_a*hi_b.
__device__ __forceinline__ void mma_tf32(float* c, uint32_t a0, uint32_t a1,
                                         uint32_t a2, uint32_t a3,
                                         uint32_t b0, uint32_t b1) {
    asm volatile(
        "mma.sync.aligned.m16n8k8.row.col.f32.tf32.tf32.f32 "
        "{%0,%1,%2,%3}, {%4,%5,%6,%7}, {%8,%9}, {%0,%1,%2,%3};\n"
        : "+f"(c[0]), "+f"(c[1]), "+f"(c[2]), "+f"(c[3])
        : "r"(a0), "r"(a1), "r"(a2), "r"(a3), "r"(b0), "r"(b1));
}

__device__ __forceinline__ uint32_t f2tf32(float f) {
    uint32_t r;
    asm("cvt.rna.tf32.f32 %0, %1;" : "=r"(r) : "f"(f));
    return r;
}

__device__ __forceinline__ void split_tf32(float v, uint32_t& hi, uint32_t& lo) {
    hi = f2tf32(v);
    lo = f2tf32(v - __uint_as_float(hi));
}

#define AS_STRIDE 36

__global__ __launch_bounds__(256) void k_gemm(const float* __restrict__ W,
                                              const float* __restrict__ embed,
                                              const int* __restrict__ x,
                                              int layer) {
    __shared__ float As[128 * AS_STRIDE];    // [row][k-chunk]
    __shared__ float WshT[128 * AS_STRIDE];  // [n][k-chunk]
    int tid = threadIdx.x;
    int wid = tid >> 5;
    int lane = tid & 31;
    int g = lane >> 2;     // 0..7
    int tig = lane & 3;    // 0..3
    int row0 = blockIdx.x * 128;
    int wrow = wid * 16;   // warp's row offset within block

    float c[16][4];
#pragma unroll
    for (int i = 0; i < 16; i++)
#pragma unroll
        for (int j = 0; j < 4; j++) c[i][j] = 0.f;

    for (int k0 = 0; k0 < DD; k0 += 32) {
        // load A tile (128 rows x 32 k) with fused input transform
        for (int idx = tid; idx < 128 * 8; idx += 256) {
            int r = idx >> 3;          // 0..127
            int k4 = (idx & 7) * 4;    // 0,4,...,28
            int row = row0 + r;
            float4 v = {0.f, 0.f, 0.f, 0.f};
            if (row < NN) {
                if (layer == 0) {
                    v = *(const float4*)&embed[x[row] * DD + k0 + k4];
                } else {
                    v = *(const float4*)&g_bufA[row * DD + k0 + k4];
                    const float* sc = &g_bn_scale[layer - 1][k0 + k4];
                    const float* sh = &g_bn_shift[layer - 1][k0 + k4];
                    v.x = tanhf(fmaf(v.x, sc[0], sh[0]));
                    v.y = tanhf(fmaf(v.y, sc[1], sh[1]));
                    v.z = tanhf(fmaf(v.z, sc[2], sh[2]));
                    v.w = tanhf(fmaf(v.w, sc[3], sh[3]));
                }
            }
            *(float4*)&As[r * AS_STRIDE + k4] = v;
        }
        // load W chunk transposed: WshT[n][kk] = W[(k0+kk)*DD + n]
        for (int idx = tid; idx < 32 * DD; idx += 256) {
            int kk = idx >> 7;       // 0..31
            int n = idx & 127;       // 0..127
            WshT[n * AS_STRIDE + kk] = W[(k0 + kk) * DD + n];
        }
        __syncthreads();
#pragma unroll
        for (int ks = 0; ks < 4; ks++) {
            int kb = ks * 8;
            float af0 = As[(wrow + g) * AS_STRIDE + kb + tig];
            float af1 = As[(wrow + g + 8) * AS_STRIDE + kb + tig];
            float af2 = As[(wrow + g) * AS_STRIDE + kb + tig + 4];
            float af3 = As[(wrow + g + 8) * AS_STRIDE + kb + tig + 4];
            uint32_t ah0, al0, ah1, al1, ah2, al2, ah3, al3;
            split_tf32(af0, ah0, al0);
            split_tf32(af1, ah1, al1);
            split_tf32(af2, ah2, al2);
            split_tf32(af3, ah3, al3);
#pragma unroll
            for (int nt = 0; nt < 16; nt++) {
                float bf0 = WshT[(nt * 8 + g) * AS_STRIDE + kb + tig];
                float bf1 = WshT[(nt * 8 + g) * AS_STRIDE + kb + tig + 4];
                uint32_t bh0, bl0, bh1, bl1;
                split_tf32(bf0, bh0, bl0);
                split_tf32(bf1, bh1, bl1);
                mma_tf32(c[nt], al0, al1, al2, al3, bh0, bh1);
                mma_tf32(c[nt], ah0, ah1, ah2, ah3, bl0, bl1);
                mma_tf32(c[nt], ah0, ah1, ah2, ah3, bh0, bh1);
            }
        }
        __syncthreads();
    }
    // epilogue: *ns[row], store
    int rA = row0 + wrow + g;
    int rB = rA + 8;
    float nsA = (rA < NN) ? g_ns[rA] : 0.f;
    float nsB = (rB < NN) ? g_ns[rB] : 0.f;
#pragma unroll
    for (int nt = 0; nt < 16; nt++) {
        int col = nt * 8 + tig * 2;
        if (rA < NN) {
            float2 o = {c[nt][0] * nsA, c[nt][1] * nsA};
            *(float2*)&g_bufB[rA * DD + col] = o;
        }
        if (rB < NN) {
            float2 o = {c[nt][2] * nsB, c[nt][3] * nsB};
            *(float2*)&g_bufB[rB * DD + col] = o;
        }
    }
}

// ---------------- aggregate + fused BN stats --------------------------------
// warp per dst node, lane handles 4 features; 4 edges in flight per iteration.
__global__ void k_agg(const float* __restrict__ bs,
                      const float* __restrict__ snorm_n,
                      int layer) {
    __shared__ float s_sum[8][DD];
    __shared__ float s_sq[8][DD];
    int w = threadIdx.x >> 5;
    int lane = threadIdx.x & 31;
    int node = blockIdx.x * 8 + w;

    float4 r = {0.f, 0.f, 0.f, 0.f};
    if (node < NN) {
        float4 acc = {0.f, 0.f, 0.f, 0.f};
        int start = g_row_ptr[node];
        int end = g_row_ptr[node + 1];
        for (int base = start; base < end; base += 32) {
            int e = base + lane;
            int s = (e < end) ? g_csr_src[e] : 0;
            int cnt = min(32, end - base);
            int j = 0;
            for (; j + 4 <= cnt; j += 4) {
                int s0 = __shfl_sync(0xffffffffu, s, j);
                int s1 = __shfl_sync(0xffffffffu, s, j + 1);
                int s2 = __shfl_sync(0xffffffffu, s, j + 2);
                int s3 = __shfl_sync(0xffffffffu, s, j + 3);
                float4 v0 = *(const float4*)&g_bufB[s0 * DD + lane * 4];
                float4 v1 = *(const float4*)&g_bufB[s1 * DD + lane * 4];
                float4 v2 = *(const float4*)&g_bufB[s2 * DD + lane * 4];
                float4 v3 = *(const float4*)&g_bufB[s3 * DD + lane * 4];
                acc.x += (v0.x + v1.x) + (v2.x + v3.x);
                acc.y += (v0.y + v1.y) + (v2.y + v3.y);
                acc.z += (v0.z + v1.z) + (v2.z + v3.z);
                acc.w += (v0.w + v1.w) + (v2.w + v3.w);
            }
            for (; j < cnt; j++) {
                int sj = __shfl_sync(0xffffffffu, s, j);
                float4 v = *(const float4*)&g_bufB[sj * DD + lane * 4];
                acc.x += v.x; acc.y += v.y; acc.z += v.z; acc.w += v.w;
            }
        }
        float ndv = g_nd[node];
        float sn = snorm_n[node];
        float4 b = *(const float4*)&bs[layer * DD + lane * 4];
        r.x = fmaf(acc.x, ndv, b.x) * sn;
        r.y = fmaf(acc.y, ndv, b.y) * sn;
        r.z = fmaf(acc.z, ndv, b.z) * sn;
        r.w = fmaf(acc.w, ndv, b.w) * sn;
        *(float4*)&g_bufA[node * DD + lane * 4] = r;
    }
    int f0 = lane * 4;
    s_sum[w][f0 + 0] = r.x; s_sum[w][f0 + 1] = r.y; s_sum[w][f0 + 2] = r.z; s_sum[w][f0 + 3] = r.w;
    s_sq[w][f0 + 0] = r.x * r.x; s_sq[w][f0 + 1] = r.y * r.y;
    s_sq[w][f0 + 2] = r.z * r.z; s_sq[w][f0 + 3] = r.w * r.w;
    __syncthreads();
    if (threadIdx.x < DD) {
        int f = threadIdx.x;
        float s = 0.f, q = 0.f;
#pragma unroll
        for (int ww = 0; ww < 8; ww++) { s += s_sum[ww][f]; q += s_sq[ww][f]; }
        atomicAdd(&g_bn_sum[layer][f], s);
        atomicAdd(&g_bn_sq[layer][f], q);
    }
}

// ---------------- BN finalize ----------
__global__ void k_bn(const float* __restrict__ gammas,
                     const float* __restrict__ betas, int layer) {
    int f = threadIdx.x;
    float mean = g_bn_sum[layer][f] * (1.f / NN);
    float var = g_bn_sq[layer][f] * (1.f / NN) - mean * mean;
    float rstd = rsqrtf(var + 1e-5f);
    float scale = rstd * gammas[layer * DD + f];
    g_bn_scale[layer][f] = scale;
    g_bn_shift[layer][f] = betas[layer * DD + f] - mean * scale;
}

// ---------------- graph mean pooling (graph_ids sorted) ----------
__global__ void k_pool(const int* __restrict__ gid) {
    int f = threadIdx.x;                 // 0..127
    int base = blockIdx.x * 32;
    float acc = 0.f;
    int cur = gid[base];
    float sc = g_bn_scale[LL - 1][f];
    float sh = g_bn_shift[LL - 1][f];
    for (int i = 0; i < 32; i++) {
        int node = base + i;
        if (node >= NN) break;
        int g = gid[node];
        if (g != cur) {
            atomicAdd(&g_pool_sum[cur * DD + f], acc);
            acc = 0.f;
            cur = g;
        }
        float v = g_bufA[node * DD + f];
        acc += tanhf(fmaf(v, sc, sh));
    }
    atomicAdd(&g_pool_sum[cur * DD + f], acc);
    if (f == 0) {
        float c = 0.f;
        int cur2 = gid[base];
        for (int i = 0; i < 32; i++) {
            int node = base + i;
            if (node >= NN) break;
            int g = gid[node];
            if (g != cur2) {
                atomicAdd(&g_pool_cnt[cur2], c);
                c = 0.f;
                cur2 = g;
            }
            c += 1.f;
        }
        atomicAdd(&g_pool_cnt[cur2], c);
    }
}

// ---------------- readout MLP ----------
__global__ void k_mlp(const float* __restrict__ r1w, const float* __restrict__ r1b,
                      const float* __restrict__ r2w, const float* __restrict__ r2b,
                      float* __restrict__ out) {
    __shared__ float hg[DD];
    __shared__ float z[64];
    int g = blockIdx.x;
    int t = threadIdx.x;  // 0..63
    float cnt = fmaxf(g_pool_cnt[g], 1.f);
    for (int f = t; f < DD; f += 64)
        hg[f] = fmaxf(g_pool_sum[g * DD + f] / cnt, 0.f);
    __syncthreads();
    float d = r1b[t];
#pragma unroll 8
    for (int f = 0; f < DD; f++) d = fmaf(hg[f], r1w[t * DD + f], d);
    z[t] = fmaxf(d, 0.f);
    __syncthreads();
    if (t == 0) {
        float o = r2b[0];
#pragma unroll 8
        for (int i = 0; i < 64; i++) o = fmaf(z[i], r2w[i], o);
        out[g] = o;
    }
}

// ---------------- host ----------
extern "C" void kernel_launch(void* const* d_in, const int* in_sizes, int n_in,
                              void* d_out, int out_size) {
    const int* x = (const int*)d_in[0];
    const int* src = (const int*)d_in[2];
    const int* dst = (const int*)d_in[3];
    const int* gid = (const int*)d_in[4];
    const float* snorm_n = (const float*)d_in[5];
    const float* embed = (const float*)d_in[7];
    const float* Ws = (const float*)d_in[8];
    const float* bs = (const float*)d_in[9];
    const float* gammas = (const float*)d_in[10];
    const float* betas = (const float*)d_in[11];
    const float* r1w = (const float*)d_in[12];
    const float* r1b = (const float*)d_in[13];
    const float* r2w = (const float*)d_in[14];
    const float* r2b = (const float*)d_in[15];
    float* out = (float*)d_out;

    k_init<<<256, 256>>>();
    k_degree<<<(EE + 255) / 256, 256>>>(src, dst);
    k_scan<<<1, 1024>>>();
    k_norms<<<(NN + 255) / 256, 256>>>();
    k_fill<<<(EE + 255) / 256, 256>>>(src, dst);

    for (int l = 0; l < LL; l++) {
        k_gemm<<<(NN + 127) / 128, 256>>>(Ws + l * DD * DD, embed, x, l);
        k_agg<<<(NN + 7) / 8, 256>>>(bs, snorm_n, l);
        k_bn<<<1, DD>>>(gammas, betas, l);
    }
    k_pool<<<(NN + 31) / 32, DD>>>(gid);
    k_mlp<<<GG, 64>>>(r1w, r1b, r2w, r2b, out);
}

// round 7
// speedup vs baseline: 1.4835x; 1.2223x over previous
#include <cuda_runtime.h>
#include <math.h>
#include <stdint.h>

#define NN 100000
#define EE 1600000
#define GG 128
#define LL 8
#define DD 128
#define EPSF 1e-5f

// ---------------- scratch (device globals; no allocation allowed) ----------
__device__ float g_bufA[NN * DD];   // node features (pre-BN output of aggregate)
__device__ float g_bufB[NN * DD];   // hw = (h@W)*ns
__device__ int   g_out_deg[NN];
__device__ int   g_in_deg[NN];
__device__ float g_ns[NN];
__device__ float g_nd[NN];
__device__ int   g_row_ptr[NN + 1];
__device__ int   g_cursor[NN];
__device__ int   g_csr_src[EE];
__device__ float g_bn_sum[LL][DD];
__device__ float g_bn_sq[LL][DD];
__device__ float g_pool_sum[GG * DD];
__device__ float g_pool_cnt[GG];

// ---------------- init ----------
__global__ void k_init() {
    int i = blockIdx.x * blockDim.x + threadIdx.x;
    int stride = gridDim.x * blockDim.x;
    for (int j = i; j < NN; j += stride) { g_out_deg[j] = 0; g_in_deg[j] = 0; }
    for (int j = i; j < LL * DD; j += stride) {
        ((float*)g_bn_sum)[j] = 0.f;
        ((float*)g_bn_sq)[j] = 0.f;
    }
    for (int j = i; j < GG * DD; j += stride) g_pool_sum[j] = 0.f;
    for (int j = i; j < GG; j += stride) g_pool_cnt[j] = 0.f;
}

// ---------------- degree counting ----------
__global__ void k_degree(const int* __restrict__ src, const int* __restrict__ dst) {
    int i = blockIdx.x * blockDim.x + threadIdx.x;
    if (i < EE) {
        atomicAdd(&g_out_deg[src[i]], 1);
        atomicAdd(&g_in_deg[dst[i]], 1);
    }
}

// ---------------- single-block exclusive scan of in-degree -> row_ptr ------
__global__ void k_scan() {
    __shared__ int wsum[32];
    __shared__ int s_running;
    int tid = threadIdx.x, lane = tid & 31, wid = tid >> 5;
    if (tid == 0) s_running = 0;
    __syncthreads();
    for (int base = 0; base < NN; base += 1024) {
        int i = base + tid;
        int v = (i < NN) ? g_in_deg[i] : 0;
        int incl = v;
#pragma unroll
        for (int off = 1; off < 32; off <<= 1) {
            int t = __shfl_up_sync(0xffffffffu, incl, off);
            if (lane >= off) incl += t;
        }
        if (lane == 31) wsum[wid] = incl;
        __syncthreads();
        if (wid == 0) {
            int s = wsum[lane];
#pragma unroll
            for (int off = 1; off < 32; off <<= 1) {
                int t = __shfl_up_sync(0xffffffffu, s, off);
                if (lane >= off) s += t;
            }
            wsum[lane] = s;
        }
        __syncthreads();
        int woff = wid ? wsum[wid - 1] : 0;
        int run = s_running;
        int excl = run + woff + incl - v;
        if (i < NN) { g_row_ptr[i] = excl; g_cursor[i] = excl; }
        __syncthreads();
        if (tid == 0) s_running = run + wsum[31];
        __syncthreads();
    }
    if (threadIdx.x == 0) g_row_ptr[NN] = s_running;
}

// ---------------- norms ----------
__global__ void k_norms() {
    int i = blockIdx.x * blockDim.x + threadIdx.x;
    if (i < NN) {
        g_ns[i] = rsqrtf((float)max(g_out_deg[i], 1));
        g_nd[i] = rsqrtf((float)max(g_in_deg[i], 1));
    }
}

// ---------------- CSR fill ----------
__global__ void k_fill(const int* __restrict__ src, const int* __restrict__ dst) {
    int i = blockIdx.x * blockDim.x + threadIdx.x;
    if (i < EE) {
        int d = dst[i];
        int p = atomicAdd(&g_cursor[d], 1);
        g_csr_src[p] = src[i];
    }
}

// ---------------- 3xBF16 tensor-core GEMM ----------------------------------
// hw = transform(h) @ W * ns[row]. Block: 128 rows, 8 warps x 16 rows.
// Markidis split: v = hi + lo (bf16 each), c += ah*bh + ah*bl + al*bh.
__device__ __forceinline__ void mma_bf16(float* c, uint32_t a0, uint32_t a1,
                                         uint32_t a2, uint32_t a3,
                                         uint32_t b0, uint32_t b1) {
    asm volatile(
        "mma.sync.aligned.m16n8k16.row.col.f32.bf16.bf16.f32 "
        "{%0,%1,%2,%3}, {%4,%5,%6,%7}, {%8,%9}, {%0,%1,%2,%3};\n"
        : "+f"(c[0]), "+f"(c[1]), "+f"(c[2]), "+f"(c[3])
        : "r"(a0), "r"(a1), "r"(a2), "r"(a3), "r"(b0), "r"(b1));
}

// pack two f32 -> bf16x2 (lo half = x, hi half = y)
__device__ __forceinline__ uint32_t pack_bf16(float x, float y) {
    uint32_t r;
    asm("cvt.rn.bf16x2.f32 %0, %1, %2;" : "=r"(r) : "f"(y), "f"(x));
    return r;
}

// split packed pair into hi-plane u32 and lo-plane u32
__device__ __forceinline__ void split2(float x, float y, uint32_t& hi, uint32_t& lo) {
    hi = pack_bf16(x, y);
    float hx = __uint_as_float(hi << 16);
    float hy = __uint_as_float(hi & 0xffff0000u);
    lo = pack_bf16(x - hx, y - hy);
}

#define PSTR 18   // pairs stride (16 data + 2 pad), conflict-free for frag loads

__global__ __launch_bounds__(256) void k_gemm(const float* __restrict__ W,
                                              const float* __restrict__ embed,
                                              const int* __restrict__ x,
                                              const float* __restrict__ gammas,
                                              const float* __restrict__ betas,
                                              int layer) {
    __shared__ uint32_t As_hi[128 * PSTR];
    __shared__ uint32_t As_lo[128 * PSTR];
    __shared__ uint32_t Wt_hi[128 * PSTR];
    __shared__ uint32_t Wt_lo[128 * PSTR];
    __shared__ float s_scale[DD];
    __shared__ float s_shift[DD];

    int tid = threadIdx.x;
    int wid = tid >> 5;
    int lane = tid & 31;
    int g = lane >> 2;     // 0..7
    int tig = lane & 3;    // 0..3
    int row0 = blockIdx.x * 128;
    int wrow = wid * 16;

    // compute BN scale/shift for (layer-1) locally — replaces k_bn
    if (layer > 0 && tid < DD) {
        int f = tid;
        float mean = g_bn_sum[layer - 1][f] * (1.f / NN);
        float var = g_bn_sq[layer - 1][f] * (1.f / NN) - mean * mean;
        float rstd = rsqrtf(var + EPSF);
        float scale = rstd * gammas[(layer - 1) * DD + f];
        s_scale[f] = scale;
        s_shift[f] = betas[(layer - 1) * DD + f] - mean * scale;
    }
    __syncthreads();

    float c[16][4];
#pragma unroll
    for (int i = 0; i < 16; i++)
#pragma unroll
        for (int j = 0; j < 4; j++) c[i][j] = 0.f;

    for (int k0 = 0; k0 < DD; k0 += 32) {
        // A tile (128 rows x 32 k) with fused input transform, split hi/lo
        for (int idx = tid; idx < 128 * 8; idx += 256) {
            int r = idx >> 3;          // 0..127
            int k4 = (idx & 7) * 4;    // 0,4,...,28
            int row = row0 + r;
            float4 v = {0.f, 0.f, 0.f, 0.f};
            if (row < NN) {
                if (layer == 0) {
                    v = *(const float4*)&embed[x[row] * DD + k0 + k4];
                } else {
                    v = *(const float4*)&g_bufA[row * DD + k0 + k4];
                    v.x = tanhf(fmaf(v.x, s_scale[k0 + k4 + 0], s_shift[k0 + k4 + 0]));
                    v.y = tanhf(fmaf(v.y, s_scale[k0 + k4 + 1], s_shift[k0 + k4 + 1]));
                    v.z = tanhf(fmaf(v.z, s_scale[k0 + k4 + 2], s_shift[k0 + k4 + 2]));
                    v.w = tanhf(fmaf(v.w, s_scale[k0 + k4 + 3], s_shift[k0 + k4 + 3]));
                }
            }
            uint32_t h01, l01, h23, l23;
            split2(v.x, v.y, h01, l01);
            split2(v.z, v.w, h23, l23);
            int p = r * PSTR + (k4 >> 1);
            As_hi[p] = h01; As_hi[p + 1] = h23;
            As_lo[p] = l01; As_lo[p + 1] = l23;
        }
        // W chunk transposed, pair-packed: Wt[n][kp] = (W[k0+2kp][n], W[k0+2kp+1][n])
        for (int idx = tid; idx < 16 * DD; idx += 256) {
            int n = idx & 127;
            int kp = idx >> 7;          // 0..15
            float w0 = W[(k0 + 2 * kp) * DD + n];
            float w1 = W[(k0 + 2 * kp + 1) * DD + n];
            uint32_t h, l;
            split2(w0, w1, h, l);
            Wt_hi[n * PSTR + kp] = h;
            Wt_lo[n * PSTR + kp] = l;
        }
        __syncthreads();
#pragma unroll
        for (int ks = 0; ks < 2; ks++) {   // two k16 steps per 32-chunk
            int kb = ks * 8;               // pair offset
            int ra = (wrow + g) * PSTR + kb + tig;
            int rb = (wrow + g + 8) * PSTR + kb + tig;
            uint32_t ah0 = As_hi[ra],     ah1 = As_hi[rb];
            uint32_t ah2 = As_hi[ra + 4], ah3 = As_hi[rb + 4];
            uint32_t al0 = As_lo[ra],     al1 = As_lo[rb];
            uint32_t al2 = As_lo[ra + 4], al3 = As_lo[rb + 4];
#pragma unroll
            for (int nt = 0; nt < 16; nt++) {
                int wb = (nt * 8 + g) * PSTR + kb + tig;
                uint32_t bh0 = Wt_hi[wb], bh1 = Wt_hi[wb + 4];
                uint32_t bl0 = Wt_lo[wb], bl1 = Wt_lo[wb + 4];
                mma_bf16(c[nt], al0, al1, al2, al3, bh0, bh1);
                mma_bf16(c[nt], ah0, ah1, ah2, ah3, bl0, bl1);
                mma_bf16(c[nt], ah0, ah1, ah2, ah3, bh0, bh1);
            }
        }
        __syncthreads();
    }
    // epilogue: *ns[row], store
    int rA = row0 + wrow + g;
    int rB = rA + 8;
    float nsA = (rA < NN) ? g_ns[rA] : 0.f;
    float nsB = (rB < NN) ? g_ns[rB] : 0.f;
#pragma unroll
    for (int nt = 0; nt < 16; nt++) {
        int col = nt * 8 + tig * 2;
        if (rA < NN) {
            float2 o = {c[nt][0] * nsA, c[nt][1] * nsA};
            *(float2*)&g_bufB[rA * DD + col] = o;
        }
        if (rB < NN) {
            float2 o = {c[nt][2] * nsB, c[nt][3] * nsB};
            *(float2*)&g_bufB[rB * DD + col] = o;
        }
    }
}

// ---------------- aggregate + fused BN stats --------------------------------
// warp per dst node, lane handles 4 features; 4 edges in flight per iteration.
__global__ void k_agg(const float* __restrict__ bs,
                      const float* __restrict__ snorm_n,
                      int layer) {
    __shared__ float s_sum[8][DD];
    __shared__ float s_sq[8][DD];
    int w = threadIdx.x >> 5;
    int lane = threadIdx.x & 31;
    int node = blockIdx.x * 8 + w;

    float4 r = {0.f, 0.f, 0.f, 0.f};
    if (node < NN) {
        float4 acc = {0.f, 0.f, 0.f, 0.f};
        int start = g_row_ptr[node];
        int end = g_row_ptr[node + 1];
        for (int base = start; base < end; base += 32) {
            int e = base + lane;
            int s = (e < end) ? g_csr_src[e] : 0;
            int cnt = min(32, end - base);
            int j = 0;
            for (; j + 4 <= cnt; j += 4) {
                int s0 = __shfl_sync(0xffffffffu, s, j);
                int s1 = __shfl_sync(0xffffffffu, s, j + 1);
                int s2 = __shfl_sync(0xffffffffu, s, j + 2);
                int s3 = __shfl_sync(0xffffffffu, s, j + 3);
                float4 v0 = *(const float4*)&g_bufB[s0 * DD + lane * 4];
                float4 v1 = *(const float4*)&g_bufB[s1 * DD + lane * 4];
                float4 v2 = *(const float4*)&g_bufB[s2 * DD + lane * 4];
                float4 v3 = *(const float4*)&g_bufB[s3 * DD + lane * 4];
                acc.x += (v0.x + v1.x) + (v2.x + v3.x);
                acc.y += (v0.y + v1.y) + (v2.y + v3.y);
                acc.z += (v0.z + v1.z) + (v2.z + v3.z);
                acc.w += (v0.w + v1.w) + (v2.w + v3.w);
            }
            for (; j < cnt; j++) {
                int sj = __shfl_sync(0xffffffffu, s, j);
                float4 v = *(const float4*)&g_bufB[sj * DD + lane * 4];
                acc.x += v.x; acc.y += v.y; acc.z += v.z; acc.w += v.w;
            }
        }
        float ndv = g_nd[node];
        float sn = snorm_n[node];
        float4 b = *(const float4*)&bs[layer * DD + lane * 4];
        r.x = fmaf(acc.x, ndv, b.x) * sn;
        r.y = fmaf(acc.y, ndv, b.y) * sn;
        r.z = fmaf(acc.z, ndv, b.z) * sn;
        r.w = fmaf(acc.w, ndv, b.w) * sn;
        *(float4*)&g_bufA[node * DD + lane * 4] = r;
    }
    int f0 = lane * 4;
    s_sum[w][f0 + 0] = r.x; s_sum[w][f0 + 1] = r.y; s_sum[w][f0 + 2] = r.z; s_sum[w][f0 + 3] = r.w;
    s_sq[w][f0 + 0] = r.x * r.x; s_sq[w][f0 + 1] = r.y * r.y;
    s_sq[w][f0 + 2] = r.z * r.z; s_sq[w][f0 + 3] = r.w * r.w;
    __syncthreads();
    if (threadIdx.x < DD) {
        int f = threadIdx.x;
        float s = 0.f, q = 0.f;
#pragma unroll
        for (int ww = 0; ww < 8; ww++) { s += s_sum[ww][f]; q += s_sq[ww][f]; }
        atomicAdd(&g_bn_sum[layer][f], s);
        atomicAdd(&g_bn_sq[layer][f], q);
    }
}

// ---------------- graph mean pooling (graph_ids sorted); BN folded in ------
__global__ void k_pool(const int* __restrict__ gid,
                       const float* __restrict__ gammas,
                       const float* __restrict__ betas) {
    int f = threadIdx.x;                 // 0..127
    int base = blockIdx.x * 32;
    // layer-7 BN scale/shift computed locally
    float mean = g_bn_sum[LL - 1][f] * (1.f / NN);
    float var = g_bn_sq[LL - 1][f] * (1.f / NN) - mean * mean;
    float rstd = rsqrtf(var + EPSF);
    float sc = rstd * gammas[(LL - 1) * DD + f];
    float sh = betas[(LL - 1) * DD + f] - mean * sc;

    float acc = 0.f;
    int cur = gid[base];
    for (int i = 0; i < 32; i++) {
        int node = base + i;
        if (node >= NN) break;
        int g = gid[node];
        if (g != cur) {
            atomicAdd(&g_pool_sum[cur * DD + f], acc);
            acc = 0.f;
            cur = g;
        }
        float v = g_bufA[node * DD + f];
        acc += tanhf(fmaf(v, sc, sh));
    }
    atomicAdd(&g_pool_sum[cur * DD + f], acc);
    if (f == 0) {
        float c = 0.f;
        int cur2 = gid[base];
        for (int i = 0; i < 32; i++) {
            int node = base + i;
            if (node >= NN) break;
            int g = gid[node];
            if (g != cur2) {
                atomicAdd(&g_pool_cnt[cur2], c);
                c = 0.f;
                cur2 = g;
            }
            c += 1.f;
        }
        atomicAdd(&g_pool_cnt[cur2], c);
    }
}

// ---------------- readout MLP ----------
__global__ void k_mlp(const float* __restrict__ r1w, const float* __restrict__ r1b,
                      const float* __restrict__ r2w, const float* __restrict__ r2b,
                      float* __restrict__ out) {
    __shared__ float hg[DD];
    __shared__ float z[64];
    int g = blockIdx.x;
    int t = threadIdx.x;  // 0..63
    float cnt = fmaxf(g_pool_cnt[g], 1.f);
    for (int f = t; f < DD; f += 64)
        hg[f] = fmaxf(g_pool_sum[g * DD + f] / cnt, 0.f);
    __syncthreads();
    float d = r1b[t];
#pragma unroll 8
    for (int f = 0; f < DD; f++) d = fmaf(hg[f], r1w[t * DD + f], d);
    z[t] = fmaxf(d, 0.f);
    __syncthreads();
    if (t == 0) {
        float o = r2b[0];
#pragma unroll 8
        for (int i = 0; i < 64; i++) o = fmaf(z[i], r2w[i], o);
        out[g] = o;
    }
}

// ---------------- host ----------
extern "C" void kernel_launch(void* const* d_in, const int* in_sizes, int n_in,
                              void* d_out, int out_size) {
    const int* x = (const int*)d_in[0];
    const int* src = (const int*)d_in[2];
    const int* dst = (const int*)d_in[3];
    const int* gid = (const int*)d_in[4];
    const float* snorm_n = (const float*)d_in[5];
    const float* embed = (const float*)d_in[7];
    const float* Ws = (const float*)d_in[8];
    const float* bs = (const float*)d_in[9];
    const float* gammas = (const float*)d_in[10];
    const float* betas = (const float*)d_in[11];
    const float* r1w = (const float*)d_in[12];
    const float* r1b = (const float*)d_in[13];
    const float* r2w = (const float*)d_in[14];
    const float* r2b = (const float*)d_in[15];
    float* out = (float*)d_out;

    k_init<<<256, 256>>>();
    k_degree<<<(EE + 255) / 256, 256>>>(src, dst);
    k_scan<<<1, 1024>>>();
    k_norms<<<(NN + 255) / 256, 256>>>();
    k_fill<<<(EE + 255) / 256, 256>>>(src, dst);

    for (int l = 0; l < LL; l++) {
        k_gemm<<<(NN + 127) / 128, 256>>>(Ws + l * DD * DD, embed, x, gammas, betas, l);
        k_agg<<<(NN + 7) / 8, 256>>>(bs, snorm_n, l);
    }
    k_pool<<<(NN + 31) / 32, DD>>>(gid, gammas, betas);
    k_mlp<<<GG, 64>>>(r1w, r1b, r2w, r2b, out);
}